// round 1
// baseline (speedup 1.0000x reference)
#include <cuda_runtime.h>

#define TT 128
#define BB 512
#define QQ 50
#define BQ (BB * QQ)
#define RSTRIDE 52          // padded row stride (floats): 52*4 % 16 == 0 -> LDS.128 aligned
#define NTHR 256
#define GAMMA_F 0.99f

// One quantile-Huber pair:
//   x  = ret_i - v_j
//   m  = min(|x|, 1)
//   h  = m * (|x| - 0.5 m)        (== 0.5 x^2 if |x|<=1 else |x|-0.5)
//   w  = (x < 0) ? 1-tau_j : tau_j  (sign test on int bits -> ALU pipe)
//   acc += w * h
#define PAIR(ri) do {                                         \
    float x_  = (ri) - vj;                                    \
    float ax_ = fabsf(x_);                                    \
    float m_  = fminf(ax_, 1.0f);                             \
    float t_  = fmaf(m_, -0.5f, ax_);                         \
    float h_  = m_ * t_;                                      \
    float w_  = (__float_as_int(x_) < 0) ? wn : tau;          \
    acc = fmaf(w_, h_, acc);                                  \
} while (0)

__global__ __launch_bounds__(NTHR)
void tdqr_loss_kernel(const float* __restrict__ reward,
                      const int*   __restrict__ step_type,
                      const float* __restrict__ discount,
                      const float* __restrict__ value,
                      const float* __restrict__ tvalue,
                      float*       __restrict__ out)
{
    __shared__ float s_ret[TT * RSTRIDE];   // staged target_value, then returns (in-place)
    __shared__ float s_part[64 * QQ];       // per-(t,j) partial sums
    __shared__ float s_r[TT];
    __shared__ float s_d[TT];
    __shared__ int   s_il[TT];

    const int b    = blockIdx.x;
    const int half = blockIdx.y;            // 0: t in [0,64), 1: t in [64,127)
    const int lo   = half * 64;
    const int hi   = half ? (TT - 1) : 64;  // loss rows [lo, hi)
    const int nt   = hi - lo;
    const int tid  = threadIdx.x;

    // ---- Stage target_value rows [lo, TT) into shared (coalesced, high MLP) ----
    const int nstage = (TT - lo) * QQ;
    for (int idx = tid; idx < nstage; idx += NTHR) {
        int tl = idx / QQ;                  // 0 .. TT-lo-1
        int q  = idx - tl * QQ;
        int t  = lo + tl;
        s_ret[t * RSTRIDE + q] = tvalue[t * BQ + b * QQ + q];
    }
    for (int t = tid; t < TT; t += NTHR) {
        s_r[t]  = reward[t * BB + b];
        s_d[t]  = discount[t * BB + b] * GAMMA_F;
        s_il[t] = (step_type[t * BB + b] == 2) ? 1 : 0;
    }
    __syncthreads();

    // ---- Backward recurrence, in place in shared (threads 0..49, one chain each) ----
    // rets[T-1] = tv[T-1];
    // rets[t]   = is_last[t] ? tv[t] : (d[t+1]*rets[t+1] + r[t+1])
    if (tid < QQ) {
        float carry = s_ret[(TT - 1) * RSTRIDE + tid];
        #pragma unroll 4
        for (int t = TT - 2; t >= lo; --t) {
            float tv_t = s_ret[t * RSTRIDE + tid];
            float acc2 = fmaf(carry, s_d[t + 1], s_r[t + 1]);
            carry = s_il[t] ? tv_t : acc2;
            s_ret[t * RSTRIDE + tid] = carry;
        }
    }
    __syncthreads();

    // ---- Pairwise quantile-Huber: one (t, j) item per thread-iteration ----
    const int nitems = nt * QQ;
    for (int g = tid; g < nitems; g += NTHR) {
        int tl = g / QQ;
        int j  = g - tl * QQ;
        int tg = lo + tl;

        float vj  = value[tg * BQ + b * QQ + j];
        float tau = ((float)j + 0.5f) * (1.0f / QQ);
        float wn  = 1.0f - tau;
        float acc = 0.0f;

        const float* rp = &s_ret[tg * RSTRIDE];
        #pragma unroll
        for (int i = 0; i < 48; i += 4) {
            float4 rr = *(const float4*)(rp + i);   // LDS.128, warp-broadcast
            PAIR(rr.x); PAIR(rr.y); PAIR(rr.z); PAIR(rr.w);
        }
        PAIR(rp[48]);
        PAIR(rp[49]);

        s_part[g] = acc;
    }
    __syncthreads();

    // ---- Deterministic fixed-order reduction over j, scale by 1/Q, write out ----
    for (int tl = tid; tl < nt; tl += NTHR) {
        float s = 0.0f;
        #pragma unroll
        for (int j = 0; j < QQ; ++j) s += s_part[tl * QQ + j];
        out[(lo + tl) * BB + b] = s * (1.0f / QQ);
    }

    // loss[T-1] = 0 (output buffer is poisoned; must be written)
    if (half == 0 && tid == 0) out[(TT - 1) * BB + b] = 0.0f;
}

extern "C" void kernel_launch(void* const* d_in, const int* in_sizes, int n_in,
                              void* d_out, int out_size)
{
    const float* reward    = (const float*)d_in[0];
    const int*   step_type = (const int*)  d_in[1];
    const float* discount  = (const float*)d_in[2];
    const float* value     = (const float*)d_in[3];
    const float* tvalue    = (const float*)d_in[4];
    float*       out       = (float*)d_out;

    dim3 grid(BB, 2);
    tdqr_loss_kernel<<<grid, NTHR>>>(reward, step_type, discount, value, tvalue, out);
}